// round 17
// baseline (speedup 1.0000x reference)
#include <cuda_runtime.h>
#include <cuda_bf16.h>

#define NB      65536
#define THREADS 192
#define SPB     32

// ---- shared memory layout (u32/f32 offsets) ----  (R5 layout)
#define OFF_WA   0        // [10][32] f32
#define OFF_WB   320      // [10][32] f32
#define OFF_W2   640      // [32][20] f32 (rows 30,31 zero)
#define OFF_W3   1280     // [20]
#define OFF_SB2  1300     // [20]
#define OFF_CW1  1320     // [6][20]
#define OFF_CB1  1440     // [6][20]
#define OFF_CW2  1560     // [6][20][12]
#define OFF_CB2  3000     // [6][12]
#define OFF_OUTW 3072     // [80]
#define OFF_MISC 3152     // [0]=sb3,[1]=out_b
#define OFF_PETA 3156     // [192]
#define OFF_C1   3348     // [78][16] u32 bf16x2
#define OFF_AB   4596     // [32][388] u32; rows A0..A11,B0..B11 of 16 u32
#define AB_STRIDE 388
#define SMEM_U32 (OFF_AB + SPB * AB_STRIDE)

extern __shared__ float smem[];

__device__ __forceinline__ unsigned f2bf(float a, float b) {
    __nv_bfloat162 h = __floats2bfloat162_rn(a, b);
    return *reinterpret_cast<unsigned*>(&h);
}
__device__ __forceinline__ __nv_bfloat162 uib(unsigned u) {
    return *reinterpret_cast<__nv_bfloat162*>(&u);
}
__device__ __forceinline__ unsigned biu(__nv_bfloat162 h) {
    return *reinterpret_cast<unsigned*>(&h);
}
// packed h1 = relu(a + b + c) in bf16x2 (fma pipe)
__device__ __forceinline__ unsigned h1pack(unsigned a, unsigned b, unsigned c,
                                           __nv_bfloat162 z2) {
    return biu(__hmax2(__hadd2(__hadd2(uib(a), uib(b)), uib(c)), z2));
}
// exact bf16 -> f32 widening
__device__ __forceinline__ float bflo(unsigned u) { return __uint_as_float(u << 16); }
__device__ __forceinline__ float bfhi(unsigned u) { return __uint_as_float(u & 0xFFFF0000u); }

__global__ void __launch_bounds__(THREADS, 2)
pin_kernel(const float* __restrict__ x_cont, const int* __restrict__ x_cat,
           const float* __restrict__ exposure,
           const float* __restrict__ cont_W1, const float* __restrict__ cont_b1,
           const float* __restrict__ cont_W2, const float* __restrict__ cont_b2,
           const float* __restrict__ cat_tables, const float* __restrict__ tokens,
           const float* __restrict__ sW1, const float* __restrict__ sb1,
           const float* __restrict__ sW2, const float* __restrict__ sb2,
           const float* __restrict__ sW3, const float* __restrict__ sb3,
           const float* __restrict__ out_w, const float* __restrict__ out_b,
           float* __restrict__ out)
{
    unsigned* smemu = (unsigned*)smem;
    const int tid  = threadIdx.x;
    const int lane = tid & 31;
    const int sub  = tid >> 5;

    // ---------------- staging ----------------
    for (int i = tid; i < 320; i += THREADS) {
        int d = i >> 5, l = i & 31;
        smem[OFF_WA + i] = (l < 30) ? sW1[d * 30 + l] : 0.f;
        smem[OFF_WB + i] = (l < 30) ? sW1[(10 + d) * 30 + l] : 0.f;
    }
    for (int i = tid; i < 640; i += THREADS) {      // W2 rows, zero-padded
        int l = i / 20, o = i % 20;
        smem[OFF_W2 + i] = (l < 30) ? sW2[l * 20 + o] : 0.f;
    }
    for (int i = tid; i < 20; i += THREADS) {
        smem[OFF_W3 + i]  = sW3[i];
        smem[OFF_SB2 + i] = sb2[i];
    }
    for (int i = tid; i < 120; i += THREADS) {
        smem[OFF_CW1 + i] = cont_W1[i];
        smem[OFF_CB1 + i] = cont_b1[i];
    }
    for (int i = tid; i < 1200; i += THREADS) {
        int c = i / 200, r = i % 200, h = r / 10, d = r % 10;
        smem[OFF_CW2 + (c * 20 + h) * 12 + d] = cont_W2[i];
    }
    for (int i = tid; i < 60; i += THREADS)
        smem[OFF_CB2 + (i / 10) * 12 + (i % 10)] = cont_b2[i];
    for (int i = tid; i < 78; i += THREADS) smem[OFF_OUTW + i] = out_w[i];
    if (tid == 0) { smem[OFF_MISC + 0] = sb3[0]; smem[OFF_MISC + 1] = out_b[0]; }
    for (int i = tid; i < 78 * 16; i += THREADS) {
        int p = i >> 4, lp = i & 15;
        int l0 = lp * 2, l1 = l0 + 1;
        float v0 = 0.f, v1 = 0.f;
        if (l0 < 30) {
            v0 = sb1[l0];
#pragma unroll
            for (int d = 0; d < 10; ++d)
                v0 = fmaf(tokens[p * 10 + d], sW1[(20 + d) * 30 + l0], v0);
        }
        if (l1 < 30) {
            v1 = sb1[l1];
#pragma unroll
            for (int d = 0; d < 10; ++d)
                v1 = fmaf(tokens[p * 10 + d], sW1[(20 + d) * 30 + l1], v1);
        }
        smemu[OFF_C1 + i] = f2bf(v0, v1);
    }
    __syncthreads();

    // ---------------- per-sample feature + projection (f32) ----------------
    const int b = blockIdx.x * SPB + lane;
    unsigned* myAB = smemu + OFF_AB + lane * AB_STRIDE;

    float e[10];
    {
        int c = sub;
        float x = x_cont[b * 6 + c];
#pragma unroll
        for (int d = 0; d < 10; ++d) e[d] = smem[OFF_CB2 + c * 12 + d];
#pragma unroll
        for (int h = 0; h < 20; ++h) {
            float hv = fmaxf(fmaf(x, smem[OFF_CW1 + c * 20 + h],
                                  smem[OFF_CB1 + c * 20 + h]), 0.f);
#pragma unroll
            for (int d = 0; d < 10; ++d)
                e[d] = fmaf(hv, smem[OFF_CW2 + (c * 20 + h) * 12 + d], e[d]);
        }
    }
#pragma unroll 1
    for (int proj = 0; proj < 2; ++proj) {
        const float* W = smem + (proj ? OFF_WB : OFF_WA);
        float acc[32];
#pragma unroll
        for (int l = 0; l < 32; ++l) acc[l] = 0.f;
#pragma unroll
        for (int d = 0; d < 10; ++d)
#pragma unroll
            for (int l = 0; l < 32; ++l)
                acc[l] = fmaf(e[d], W[d * 32 + l], acc[l]);
        unsigned* dst = myAB + (proj ? (12 + sub) : sub) * 16;
#pragma unroll
        for (int i = 0; i < 16; ++i) dst[i] = f2bf(acc[2 * i], acc[2 * i + 1]);
    }
    {
        int c = sub;
        int idx = x_cat[b * 6 + c];
        const float2* row = (const float2*)(cat_tables + (size_t)(c * 100 + idx) * 10);
#pragma unroll
        for (int d = 0; d < 5; ++d) { float2 v = row[d]; e[2*d] = v.x; e[2*d+1] = v.y; }
    }
#pragma unroll 1
    for (int proj = 0; proj < 2; ++proj) {
        const float* W = smem + (proj ? OFF_WB : OFF_WA);
        float acc[32];
#pragma unroll
        for (int l = 0; l < 32; ++l) acc[l] = 0.f;
#pragma unroll
        for (int d = 0; d < 10; ++d)
#pragma unroll
            for (int l = 0; l < 32; ++l)
                acc[l] = fmaf(e[d], W[d * 32 + l], acc[l]);
        unsigned* dst = myAB + (proj ? (18 + sub) : (6 + sub)) * 16;
#pragma unroll
        for (int i = 0; i < 16; ++i) dst[i] = f2bf(acc[2 * i], acc[2 * i + 1]);
    }
    __syncthreads();

    // ---------------- pair loop: rows {sub, 11-sub} = 13 pairs ----------------
    const float raw_bias = smem[OFF_MISC + 0];
    const __nv_bfloat162 z2 = __floats2bfloat162_rn(0.f, 0.f);
    float eta = 0.f;

    // one interaction group: 8 h1 rows (from hoisted A quad) -> h2 accumulation
#define GBLOCK(AREG, G)                                                     \
    {                                                                       \
        uint4 bb = Bk[G], cc = Cp[G];                                       \
        unsigned p0 = h1pack(AREG.x, bb.x, cc.x, z2);                       \
        unsigned p1 = h1pack(AREG.y, bb.y, cc.y, z2);                       \
        unsigned p2 = h1pack(AREG.z, bb.z, cc.z, z2);                       \
        unsigned p3 = h1pack(AREG.w, bb.w, cc.w, z2);                       \
        float h1[8];                                                        \
        h1[0] = bflo(p0); h1[1] = bfhi(p0);                                 \
        h1[2] = bflo(p1); h1[3] = bfhi(p1);                                 \
        h1[4] = bflo(p2); h1[5] = bfhi(p2);                                 \
        h1[6] = bflo(p3); h1[7] = bfhi(p3);                                 \
        const float* w2b = smem + OFF_W2 + (G) * 160;                       \
        _Pragma("unroll 2")                                                 \
        for (int i = 0; i < 8; ++i) {                                       \
            const float4* wr = (const float4*)(w2b + i * 20);               \
            float4 w0 = wr[0], w1 = wr[1], w2v = wr[2], w3v = wr[3], w4 = wr[4]; \
            float h = h1[i];                                                \
            h2[0]  = fmaf(h, w0.x, h2[0]);  h2[1]  = fmaf(h, w0.y, h2[1]);  \
            h2[2]  = fmaf(h, w0.z, h2[2]);  h2[3]  = fmaf(h, w0.w, h2[3]);  \
            h2[4]  = fmaf(h, w1.x, h2[4]);  h2[5]  = fmaf(h, w1.y, h2[5]);  \
            h2[6]  = fmaf(h, w1.z, h2[6]);  h2[7]  = fmaf(h, w1.w, h2[7]);  \
            h2[8]  = fmaf(h, w2v.x, h2[8]); h2[9]  = fmaf(h, w2v.y, h2[9]); \
            h2[10] = fmaf(h, w2v.z, h2[10]);h2[11] = fmaf(h, w2v.w, h2[11]);\
            h2[12] = fmaf(h, w3v.x, h2[12]);h2[13] = fmaf(h, w3v.y, h2[13]);\
            h2[14] = fmaf(h, w3v.z, h2[14]);h2[15] = fmaf(h, w3v.w, h2[15]);\
            h2[16] = fmaf(h, w4.x, h2[16]); h2[17] = fmaf(h, w4.y, h2[17]); \
            h2[18] = fmaf(h, w4.z, h2[18]); h2[19] = fmaf(h, w4.w, h2[19]); \
        }                                                                   \
    }

#pragma unroll 1
    for (int r = 0; r < 2; ++r) {
        const int j = r ? (11 - sub) : sub;
        const int pbase = (j * (25 - j)) >> 1;
        const uint4* AjP = (const uint4*)(myAB + j * 16);
        uint4 A0 = AjP[0], A1 = AjP[1], A2 = AjP[2], A3 = AjP[3];

#pragma unroll 1
        for (int k = j; k < 12; ++k) {
            const int p = pbase + (k - j);
            const uint4* Bk = (const uint4*)(myAB + (12 + k) * 16);
            const uint4* Cp = (const uint4*)(smemu + OFF_C1 + p * 16);

            float h2[20];
            {
                const float4* sb = (const float4*)(smem + OFF_SB2);
#pragma unroll
                for (int v = 0; v < 5; ++v) {
                    float4 s = sb[v];
                    h2[v*4+0]=s.x; h2[v*4+1]=s.y; h2[v*4+2]=s.z; h2[v*4+3]=s.w;
                }
            }

            GBLOCK(A0, 0)
            GBLOCK(A1, 1)
            GBLOCK(A2, 2)
            GBLOCK(A3, 3)

            float raw = raw_bias;
            {
                const float4* w3r = (const float4*)(smem + OFF_W3);
#pragma unroll
                for (int v = 0; v < 5; ++v) {
                    float4 w = w3r[v];
                    raw = fmaf(fmaxf(h2[v*4+0], 0.f), w.x, raw);
                    raw = fmaf(fmaxf(h2[v*4+1], 0.f), w.y, raw);
                    raw = fmaf(fmaxf(h2[v*4+2], 0.f), w.z, raw);
                    raw = fmaf(fmaxf(h2[v*4+3], 0.f), w.w, raw);
                }
            }
            float ht = fminf(fmaxf(raw * (1.f/6.f) + 0.5f, 0.f), 1.f) - 0.5f;
            eta = fmaf(smem[OFF_OUTW + p], ht, eta);
        }
    }

    smem[OFF_PETA + tid] = eta;
    __syncthreads();
    if (tid < 32) {
        float esum = 0.f;
#pragma unroll
        for (int s = 0; s < 6; ++s) esum += smem[OFF_PETA + tid + 32 * s];
        esum += smem[OFF_MISC + 1];
        esum = fminf(fmaxf(esum, -20.f), 20.f);
        out[b] = __expf(esum) * exposure[b];
    }
}

extern "C" void kernel_launch(void* const* d_in, const int* in_sizes, int n_in,
                              void* d_out, int out_size)
{
    (void)in_sizes; (void)n_in; (void)out_size;
    size_t shmem = SMEM_U32 * 4;
    cudaFuncSetAttribute(pin_kernel, cudaFuncAttributeMaxDynamicSharedMemorySize,
                         (int)shmem);
    pin_kernel<<<NB / SPB, THREADS, shmem>>>(
        (const float*)d_in[0],  (const int*)d_in[1],   (const float*)d_in[2],
        (const float*)d_in[3],  (const float*)d_in[4], (const float*)d_in[5],
        (const float*)d_in[6],  (const float*)d_in[7], (const float*)d_in[8],
        (const float*)d_in[9],  (const float*)d_in[10],(const float*)d_in[11],
        (const float*)d_in[12], (const float*)d_in[13],(const float*)d_in[14],
        (const float*)d_in[15], (const float*)d_in[16],
        (float*)d_out);
}